// round 15
// baseline (speedup 1.0000x reference)
#include <cuda_runtime.h>
#include <cstdint>

#define NB    16
#define PIX   784
#define NPOS  12544
#define CIN   1024
#define WIDTH 256
#define COUT  1024

// -------- device scratch --------
__device__ uint32_t g_x8[NPOS * CIN / 4];
__device__ int8_t   g_xn[NPOS * CIN];      // NCHW int8 copy of x (residual path)
__device__ uint32_t g_w1[WIDTH * CIN / 4];
__device__ uint32_t g_w2[WIDTH * 9 * WIDTH / 4];
__device__ uint32_t g_w3[COUT * WIDTH / 4];
__device__ uint32_t g_a1[NPOS * WIDTH / 4];
__device__ uint32_t g_a2[NPOS * WIDTH / 4];

static __device__ __forceinline__ uint32_t pack4(int v0, int v1, int v2, int v3) {
    return (uint32_t)(uint8_t)(int8_t)v0 |
           ((uint32_t)(uint8_t)(int8_t)v1 << 8) |
           ((uint32_t)(uint8_t)(int8_t)v2 << 16) |
           ((uint32_t)(uint8_t)(int8_t)v3 << 24);
}

static __device__ __forceinline__ int bn_clip_relu(int acc, float a, float b, float qq) {
    float t = __fadd_rn(__fmul_rn(a, (float)acc), __fmul_rn(b, qq));
    float r = rintf(t * (1.0f / 4096.0f));
    r = fminf(fmaxf(r, -128.0f), 127.0f);
    return (int)fmaxf(r, 0.0f);
}
static __device__ __forceinline__ float bn_clip(int acc, float a, float b, float qq) {
    float t = __fadd_rn(__fmul_rn(a, (float)acc), __fmul_rn(b, qq));
    float r = rintf(t * (1.0f / 4096.0f));
    return fminf(fmaxf(r, -128.0f), 127.0f);
}

__device__ __forceinline__ uint32_t smem_u32(const void* p) {
    uint32_t a;
    asm("{ .reg .u64 t; cvta.to.shared.u64 t, %1; cvt.u32.u64 %0, t; }" : "=r"(a) : "l"(p));
    return a;
}

#define CP16(dst, src)        asm volatile("cp.async.cg.shared.global [%0], [%1], 16;" :: "r"(dst), "l"(src))
#define CP16CA(dst, src)      asm volatile("cp.async.ca.shared.global [%0], [%1], 16;" :: "r"(dst), "l"(src))
#define CP16Z(dst, src, pred) asm volatile("cp.async.cg.shared.global [%0], [%1], 16, %2;" :: "r"(dst), "l"(src), "r"((pred) ? 16 : 0))
#define CP_COMMIT()           asm volatile("cp.async.commit_group;" ::: "memory")
#define CP_WAIT2()            asm volatile("cp.async.wait_group 2;" ::: "memory")
#define CP_WAIT1()            asm volatile("cp.async.wait_group 1;" ::: "memory")

// -------------------- fused prep: weight packing + input transpose --------------------
#define W1W (WIDTH * CIN / 4)
#define W2W (WIDTH * 9 * WIDTH / 4)
#define W3W (COUT * WIDTH / 4)
#define PACK_BLOCKS ((W1W + W2W + W3W + 255) / 256)   // 1092
#define XPOSE_BLOCKS (25 * 8 * 16)                    // 3200

__global__ void prep_kernel(const float* __restrict__ w1, const int* __restrict__ s1,
                            const float* __restrict__ w2, const int* __restrict__ s2,
                            const float* __restrict__ w3, const int* __restrict__ s3,
                            const int* __restrict__ x) {
    int b = blockIdx.x;
    int t = threadIdx.x;
    if (b < PACK_BLOCKS) {
        int wi = b * 256 + t;
        if (wi < W1W) {
            int v[4];
#pragma unroll
            for (int j = 0; j < 4; j++) { int idx = wi * 4 + j; v[j] = (int)w1[idx] * (1 << s1[idx]); }
            g_w1[wi] = pack4(v[0], v[1], v[2], v[3]);
        } else if (wi < W1W + W2W) {
            int k = wi - W1W;
            int co  = k / 576;
            int rr  = k - co * 576;
            int tap = rr >> 6;
            int cw  = rr & 63;
            int v[4];
#pragma unroll
            for (int j = 0; j < 4; j++) {
                int ci  = cw * 4 + j;
                int src = co * 2304 + ci * 9 + tap;
                v[j] = (int)w2[src] * (1 << s2[src]);
            }
            g_w2[k] = pack4(v[0], v[1], v[2], v[3]);
        } else if (wi < W1W + W2W + W3W) {
            int k = wi - W1W - W2W;
            int v[4];
#pragma unroll
            for (int j = 0; j < 4; j++) { int idx = k * 4 + j; v[j] = (int)w3[idx] * (1 << s3[idx]); }
            g_w3[k] = pack4(v[0], v[1], v[2], v[3]);
        }
        return;
    }
    int xb = b - PACK_BLOCKS;
    int bx = xb % 25;
    int by = (xb / 25) & 7;
    int n  = xb / 200;

    __shared__ uint32_t s[32][33];
    int phw_l = t & 31, phw = bx * 32 + phw_l;
#pragma unroll
    for (int l = 0; l < 4; l++) {
        int cwl = (t >> 5) + l * 8;
        uint32_t wv = 0;
        if (phw < PIX) {
            int ci = by * 128 + cwl * 4;
            size_t base = ((size_t)n * CIN + ci) * PIX + phw;
            const int* p = x + base;
            int v0 = p[0], v1 = p[PIX], v2 = p[2 * PIX], v3 = p[3 * PIX];
            wv = pack4(v0, v1, v2, v3);
            // NCHW int8 copy for the residual path (32B coalesced per warp)
            g_xn[base]           = (int8_t)v0;
            g_xn[base + PIX]     = (int8_t)v1;
            g_xn[base + 2 * PIX] = (int8_t)v2;
            g_xn[base + 3 * PIX] = (int8_t)v3;
        }
        s[phw_l][cwl] = wv;
    }
    __syncthreads();
    int cwl2 = t & 31;
#pragma unroll
    for (int l = 0; l < 4; l++) {
        int pl = (t >> 5) + l * 8;
        int phw2 = bx * 32 + pl;
        if (phw2 < PIX)
            g_x8[((size_t)(n * PIX + phw2)) * 256 + by * 32 + cwl2] = s[pl][cwl2];
    }
}

// -------------------- IMMA tile machinery --------------------
#define RS      80
#define STAGES  4
#define ABUF    (64 * RS)
#define BBUF    (128 * RS)
#define SMEM12  (STAGES * (ABUF + BBUF))   // 61440
#define STAGES3 3
#define SMEM3   (2 * STAGES3 * BBUF)       // 61440

// warp tile 32 pos x 32 co (conv1/2)
__device__ __forceinline__ void compute_chunk64(uint32_t saBuf, uint32_t sbBuf,
                                                int m0, int n0, int lane,
                                                int acc[2][4][4]) {
#pragma unroll
    for (int ks = 0; ks < 2; ks++) {
        uint32_t af[2][4];
        uint32_t bf[4][2];
#pragma unroll
        for (int mi = 0; mi < 2; mi++) {
            uint32_t addr = saBuf + (uint32_t)((m0 + mi * 16 + (lane & 15)) * RS + ks * 32 + ((lane >> 4) << 4));
            asm volatile("ldmatrix.sync.aligned.m8n8.x4.shared.b16 {%0,%1,%2,%3}, [%4];"
                         : "=r"(af[mi][0]), "=r"(af[mi][1]), "=r"(af[mi][2]), "=r"(af[mi][3])
                         : "r"(addr));
        }
#pragma unroll
        for (int np = 0; np < 2; np++) {
            int rowb = n0 + np * 16 + ((lane >> 4) << 3) + (lane & 7);
            uint32_t addr = sbBuf + (uint32_t)(rowb * RS + ks * 32 + (((lane >> 3) & 1) << 4));
            asm volatile("ldmatrix.sync.aligned.m8n8.x4.shared.b16 {%0,%1,%2,%3}, [%4];"
                         : "=r"(bf[np * 2][0]), "=r"(bf[np * 2][1]),
                           "=r"(bf[np * 2 + 1][0]), "=r"(bf[np * 2 + 1][1])
                         : "r"(addr));
        }
#pragma unroll
        for (int mi = 0; mi < 2; mi++)
#pragma unroll
            for (int ni = 0; ni < 4; ni++)
                asm volatile("mma.sync.aligned.m16n8k32.row.col.s32.s8.s8.s32 "
                             "{%0,%1,%2,%3}, {%4,%5,%6,%7}, {%8,%9}, {%0,%1,%2,%3};"
                             : "+r"(acc[mi][ni][0]), "+r"(acc[mi][ni][1]),
                               "+r"(acc[mi][ni][2]), "+r"(acc[mi][ni][3])
                             : "r"(af[mi][0]), "r"(af[mi][1]), "r"(af[mi][2]), "r"(af[mi][3]),
                               "r"(bf[ni][0]), "r"(bf[ni][1]));
    }
}

// warp tile 64 pos x 32 co (conv3)
__device__ __forceinline__ void compute_chunk128(uint32_t saBuf, uint32_t sbBuf,
                                                 int m0, int n0, int lane,
                                                 int acc[4][4][4]) {
#pragma unroll
    for (int ks = 0; ks < 2; ks++) {
        uint32_t af[4][4];
        uint32_t bf[4][2];
#pragma unroll
        for (int mi = 0; mi < 4; mi++) {
            uint32_t addr = saBuf + (uint32_t)((m0 + mi * 16 + (lane & 15)) * RS + ks * 32 + ((lane >> 4) << 4));
            asm volatile("ldmatrix.sync.aligned.m8n8.x4.shared.b16 {%0,%1,%2,%3}, [%4];"
                         : "=r"(af[mi][0]), "=r"(af[mi][1]), "=r"(af[mi][2]), "=r"(af[mi][3])
                         : "r"(addr));
        }
#pragma unroll
        for (int np = 0; np < 2; np++) {
            int rowb = n0 + np * 16 + ((lane >> 4) << 3) + (lane & 7);
            uint32_t addr = sbBuf + (uint32_t)(rowb * RS + ks * 32 + (((lane >> 3) & 1) << 4));
            asm volatile("ldmatrix.sync.aligned.m8n8.x4.shared.b16 {%0,%1,%2,%3}, [%4];"
                         : "=r"(bf[np * 2][0]), "=r"(bf[np * 2][1]),
                           "=r"(bf[np * 2 + 1][0]), "=r"(bf[np * 2 + 1][1])
                         : "r"(addr));
        }
#pragma unroll
        for (int mi = 0; mi < 4; mi++)
#pragma unroll
            for (int ni = 0; ni < 4; ni++)
                asm volatile("mma.sync.aligned.m16n8k32.row.col.s32.s8.s8.s32 "
                             "{%0,%1,%2,%3}, {%4,%5,%6,%7}, {%8,%9}, {%0,%1,%2,%3};"
                             : "+r"(acc[mi][ni][0]), "+r"(acc[mi][ni][1]),
                               "+r"(acc[mi][ni][2]), "+r"(acc[mi][ni][3])
                             : "r"(af[mi][0]), "r"(af[mi][1]), "r"(af[mi][2]), "r"(af[mi][3]),
                               "r"(bf[ni][0]), "r"(bf[ni][1]));
    }
}

// ---- coalesced epilogue for conv1/conv2 ----
#define EP_RS 136
__device__ __forceinline__ void epi_act_coal(int acc[2][4][4], int posBase, int coBase,
                                             int m0, int n0, int t, int lane, int wid,
                                             int8_t* smem,
                                             const float* __restrict__ alpha,
                                             const float* __restrict__ beta,
                                             const int* __restrict__ q,
                                             uint32_t* __restrict__ dstw) {
    int*   sacc = (int*)smem;
    float* sal  = (float*)(smem + 64 * EP_RS * 4);
    float* sbe  = sal + 128;
    float* sqq  = sbe + 128;

    __syncthreads();
    if (t < 128) {
        int co = coBase + t;
        sal[t] = alpha[co];
        sbe[t] = beta[co];
        sqq[t] = exp2f((float)(q[co] + 12));
    }
#pragma unroll
    for (int mi = 0; mi < 2; mi++) {
#pragma unroll
        for (int ni = 0; ni < 4; ni++) {
            int pl = m0 + mi * 16 + (lane >> 2);
            int cl = n0 + ni * 8 + (lane & 3) * 2;
            sacc[pl * EP_RS + cl]           = acc[mi][ni][0];
            sacc[pl * EP_RS + cl + 1]       = acc[mi][ni][1];
            sacc[(pl + 8) * EP_RS + cl]     = acc[mi][ni][2];
            sacc[(pl + 8) * EP_RS + cl + 1] = acc[mi][ni][3];
        }
    }
    __syncthreads();
#pragma unroll
    for (int it = 0; it < 8; it++) {
        int pl = wid + it * 8;
        int cb = lane * 4;
        int4 v = *(int4*)&sacc[pl * EP_RS + cb];
        int b0 = bn_clip_relu(v.x, sal[cb],     sbe[cb],     sqq[cb]);
        int b1 = bn_clip_relu(v.y, sal[cb + 1], sbe[cb + 1], sqq[cb + 1]);
        int b2 = bn_clip_relu(v.z, sal[cb + 2], sbe[cb + 2], sqq[cb + 2]);
        int b3 = bn_clip_relu(v.w, sal[cb + 3], sbe[cb + 3], sqq[cb + 3]);
        dstw[(size_t)(posBase + pl) * 64 + (coBase >> 2) + lane] = pack4(b0, b1, b2, b3);
    }
}

// -------------------- conv1: tile 64x128, K=1024 (16 chunks) --------------------
__global__ void __launch_bounds__(256, 3) conv1_imma(const float* __restrict__ alpha,
                                                     const float* __restrict__ beta,
                                                     const int* __restrict__ q) {
    extern __shared__ int8_t smem[];
    int8_t* sA = smem;
    int8_t* sB = smem + STAGES * ABUF;
    int t = threadIdx.x, lane = t & 31, wid = t >> 5;
    int m0 = (wid >> 2) * 32, n0 = (wid & 3) * 32;
    int posBase = blockIdx.x * 64, coBase = blockIdx.y * 128;
    uint32_t sa32 = smem_u32(sA), sb32 = smem_u32(sB);
    const int8_t* gx = (const int8_t*)g_x8;
    const int8_t* gw = (const int8_t*)g_w1;

    int acc[2][4][4];
#pragma unroll
    for (int i = 0; i < 2; i++)
#pragma unroll
        for (int j = 0; j < 4; j++)
#pragma unroll
            for (int k = 0; k < 4; k++) acc[i][j][k] = 0;

    int rowA = t >> 2, offA = (t & 3) * 16;
    int rowB = t >> 1, offB = (t & 1) * 32;
    uint32_t dA = sa32 + rowA * RS + offA;
    uint32_t dB = sb32 + rowB * RS + offB;
    const int8_t* gA = gx + (size_t)(posBase + rowA) * CIN + offA;
    const int8_t* gB = gw + (size_t)(coBase + rowB) * CIN + offB;

    auto load = [&](int ch) {
        int st = ch & 3;
        CP16(dA + st * ABUF, gA + ch * 64);
        CP16CA(dB + st * BBUF,      gB + ch * 64);
        CP16CA(dB + st * BBUF + 16, gB + ch * 64 + 16);
    };

    load(0); CP_COMMIT(); load(1); CP_COMMIT(); load(2); CP_COMMIT();
    const int NCH = 16;
    for (int ch = 0; ch < NCH; ch++) {
        CP_WAIT2();
        __syncthreads();
        if (ch + 3 < NCH) load(ch + 3);
        CP_COMMIT();
        compute_chunk64(sa32 + (ch & 3) * ABUF, sb32 + (ch & 3) * BBUF, m0, n0, lane, acc);
    }
    epi_act_coal(acc, posBase, coBase, m0, n0, t, lane, wid, smem, alpha, beta, q, g_a1);
}

// -------------------- conv2: tile 64x128, 36 chunks --------------------
__global__ void __launch_bounds__(256, 3) conv2_imma(const float* __restrict__ alpha,
                                                     const float* __restrict__ beta,
                                                     const int* __restrict__ q) {
    extern __shared__ int8_t smem[];
    int8_t* sA = smem;
    int8_t* sB = smem + STAGES * ABUF;
    int t = threadIdx.x, lane = t & 31, wid = t >> 5;
    int m0 = (wid >> 2) * 32, n0 = (wid & 3) * 32;
    int posBase = blockIdx.x * 64, coBase = blockIdx.y * 128;
    uint32_t sa32 = smem_u32(sA), sb32 = smem_u32(sB);
    const int8_t* ga1 = (const int8_t*)g_a1;
    const int8_t* gw = (const int8_t*)g_w2;

    int acc[2][4][4];
#pragma unroll
    for (int i = 0; i < 2; i++)
#pragma unroll
        for (int j = 0; j < 4; j++)
#pragma unroll
            for (int k = 0; k < 4; k++) acc[i][j][k] = 0;

    int rowA = t >> 2, offA = (t & 3) * 16;
    int rowB = t >> 1, offB = (t & 1) * 32;
    uint32_t dA = sa32 + rowA * RS + offA;
    uint32_t dB = sb32 + rowB * RS + offB;
    int pos = posBase + rowA;
    int pimg = pos / PIX, prem = pos - pimg * PIX;
    int py = prem / 28, px = prem - py * 28;
    const int8_t* gB = gw + (size_t)(coBase + rowB) * 2304 + offB;

    auto load = [&](int ch) {
        int st = ch & 3;
        int tap = ch >> 2, kc = ch & 3;
        int dy = tap / 3 - 1, dx = tap - (tap / 3) * 3 - 1;
        int ys = py + dy, xs = px + dx;
        bool ok = (ys >= 0 && ys < 28 && xs >= 0 && xs < 28);
        const int8_t* gA = ga1 + ((size_t)(pimg * PIX + ys * 28 + xs) * WIDTH) + kc * 64 + offA;
        CP16Z(dA + st * ABUF, gA, ok);
        CP16CA(dB + st * BBUF,      gB + ch * 64);
        CP16CA(dB + st * BBUF + 16, gB + ch * 64 + 16);
    };

    load(0); CP_COMMIT(); load(1); CP_COMMIT(); load(2); CP_COMMIT();
    const int NCH = 36;
    for (int ch = 0; ch < NCH; ch++) {
        CP_WAIT2();
        __syncthreads();
        if (ch + 3 < NCH) load(ch + 3);
        CP_COMMIT();
        compute_chunk64(sa32 + (ch & 3) * ABUF, sb32 + (ch & 3) * BBUF, m0, n0, lane, acc);
    }
    epi_act_coal(acc, posBase, coBase, m0, n0, t, lane, wid, smem, alpha, beta, q, g_a2);
}

// -------------------- conv3: tile 128x128, K=256 (4 chunks), 3-stage, + residual --------------------
#define EP3_RS 68
__global__ void __launch_bounds__(256, 3) conv3_imma(const float* __restrict__ alpha,
                                                     const float* __restrict__ beta,
                                                     const int* __restrict__ q,
                                                     float* __restrict__ out) {
    extern __shared__ int8_t smem[];
    int8_t* sA = smem;
    int8_t* sB = smem + STAGES3 * BBUF;
    int t = threadIdx.x, lane = t & 31, wid = t >> 5;
    int m0 = (wid >> 2) * 64, n0 = (wid & 3) * 32;
    int posBase = blockIdx.x * 128, coBase = blockIdx.y * 128;
    uint32_t sa32 = smem_u32(sA), sb32 = smem_u32(sB);
    const int8_t* ga2 = (const int8_t*)g_a2;
    const int8_t* gw = (const int8_t*)g_w3;

    int acc[4][4][4];
#pragma unroll
    for (int i = 0; i < 4; i++)
#pragma unroll
        for (int j = 0; j < 4; j++)
#pragma unroll
            for (int k = 0; k < 4; k++) acc[i][j][k] = 0;

    int row = t >> 1, off = (t & 1) * 32;
    uint32_t dA = sa32 + row * RS + off;
    uint32_t dB = sb32 + row * RS + off;
    const int8_t* gA = ga2 + (size_t)(posBase + row) * WIDTH + off;
    const int8_t* gB = gw + (size_t)(coBase + row) * WIDTH + off;

    auto load = [&](int ch) {
        int st = ch % STAGES3;
        CP16(dA + st * BBUF,      gA + ch * 64);
        CP16(dA + st * BBUF + 16, gA + ch * 64 + 16);
        CP16CA(dB + st * BBUF,      gB + ch * 64);
        CP16CA(dB + st * BBUF + 16, gB + ch * 64 + 16);
    };

    load(0); CP_COMMIT(); load(1); CP_COMMIT();
    const int NCH = 4;
    for (int ch = 0; ch < NCH; ch++) {
        CP_WAIT1();
        __syncthreads();
        if (ch + 2 < NCH) load(ch + 2);
        CP_COMMIT();
        compute_chunk128(sa32 + (ch % STAGES3) * BBUF, sb32 + (ch % STAGES3) * BBUF, m0, n0, lane, acc);
    }

    int*   sacc = (int*)smem;
    float* sal  = (float*)(smem + 128 * EP3_RS * 4);
    float* sbe  = sal + 128;
    float* sqq  = sbe + 128;

    __syncthreads();
    if (t < 128) {
        int co = coBase + t;
        sal[t] = alpha[co];
        sbe[t] = beta[co];
        sqq[t] = exp2f((float)(q[co] + 12));
    }

#pragma unroll
    for (int pass = 0; pass < 2; pass++) {
        if (pass) __syncthreads();
#pragma unroll
        for (int mi2 = 0; mi2 < 2; mi2++) {
            int mi = pass * 2 + mi2;
#pragma unroll
            for (int ni = 0; ni < 4; ni++) {
#pragma unroll
                for (int k = 0; k < 4; k++) {
                    int pl = m0 + mi * 16 + (lane >> 2) + (k >> 1) * 8;
                    int r  = (pl & 31) + ((pl >> 6) * 32);
                    int cl = n0 + ni * 8 + (lane & 3) * 2 + (k & 1);
                    sacc[cl * EP3_RS + r] = acc[mi][ni][k];
                }
            }
        }
        __syncthreads();
#pragma unroll
        for (int it = 0; it < 32; it++) {
            int cl = wid * 16 + (it >> 1);
            int r  = (it & 1) * 32 + lane;
            int pl = (r & 31) + ((r >> 5) * 64) + pass * 32;
            int pos = posBase + pl;
            int n = pos / PIX, rem = pos - n * PIX;
            int co = coBase + cl;
            int av = sacc[cl * EP3_RS + r];
            float v = bn_clip(av, sal[cl], sbe[cl], sqq[cl]);
            size_t gi = ((size_t)n * COUT + co) * PIX + rem;
            float s = v + (float)g_xn[gi];
            out[gi] = fminf(fmaxf(s, 0.0f), 127.0f);
        }
    }
}

// -------------------- launch --------------------
extern "C" void kernel_launch(void* const* d_in, const int* in_sizes, int n_in,
                              void* d_out, int out_size) {
    const int*   x   = (const int*)d_in[0];
    const float* w21 = (const float*)d_in[1];
    const int*   s1  = (const int*)d_in[2];
    const float* w22 = (const float*)d_in[3];
    const int*   s2  = (const int*)d_in[4];
    const float* w23 = (const float*)d_in[5];
    const int*   s3  = (const int*)d_in[6];
    const float* al1 = (const float*)d_in[7];
    const float* be1 = (const float*)d_in[8];
    const int*   q1  = (const int*)d_in[9];
    const float* al2 = (const float*)d_in[10];
    const float* be2 = (const float*)d_in[11];
    const int*   q2  = (const int*)d_in[12];
    const float* al3 = (const float*)d_in[13];
    const float* be3 = (const float*)d_in[14];
    const int*   q3  = (const int*)d_in[15];
    float* out = (float*)d_out;

    cudaFuncSetAttribute(conv1_imma, cudaFuncAttributeMaxDynamicSharedMemorySize, SMEM12);
    cudaFuncSetAttribute(conv2_imma, cudaFuncAttributeMaxDynamicSharedMemorySize, SMEM12);
    cudaFuncSetAttribute(conv3_imma, cudaFuncAttributeMaxDynamicSharedMemorySize, SMEM3);

    prep_kernel<<<PACK_BLOCKS + XPOSE_BLOCKS, 256>>>(w21, s1, w22, s2, w23, s3, x);

    conv1_imma<<<dim3(196, 2), 256, SMEM12>>>(al1, be1, q1);
    conv2_imma<<<dim3(196, 2), 256, SMEM12>>>(al2, be2, q2);
    conv3_imma<<<dim3(98, 8), 256, SMEM3>>>(al3, be3, q3, out);
}

// round 17
// speedup vs baseline: 1.2046x; 1.2046x over previous
#include <cuda_runtime.h>
#include <cstdint>

#define NB    16
#define PIX   784
#define NPOS  12544
#define CIN   1024
#define WIDTH 256
#define COUT  1024

// -------- device scratch --------
__device__ uint32_t g_x8[NPOS * CIN / 4];
__device__ uint32_t g_w1[WIDTH * CIN / 4];
__device__ uint32_t g_w2[WIDTH * 9 * WIDTH / 4];
__device__ uint32_t g_w3[COUT * WIDTH / 4];
__device__ uint32_t g_a1[NPOS * WIDTH / 4];
__device__ uint32_t g_a2[NPOS * WIDTH / 4];

static __device__ __forceinline__ uint32_t pack4(int v0, int v1, int v2, int v3) {
    return (uint32_t)(uint8_t)(int8_t)v0 |
           ((uint32_t)(uint8_t)(int8_t)v1 << 8) |
           ((uint32_t)(uint8_t)(int8_t)v2 << 16) |
           ((uint32_t)(uint8_t)(int8_t)v3 << 24);
}

static __device__ __forceinline__ int bn_clip_relu(int acc, float a, float b, float qq) {
    float t = __fadd_rn(__fmul_rn(a, (float)acc), __fmul_rn(b, qq));
    float r = rintf(t * (1.0f / 4096.0f));
    r = fminf(fmaxf(r, -128.0f), 127.0f);
    return (int)fmaxf(r, 0.0f);
}
static __device__ __forceinline__ float bn_clip(int acc, float a, float b, float qq) {
    float t = __fadd_rn(__fmul_rn(a, (float)acc), __fmul_rn(b, qq));
    float r = rintf(t * (1.0f / 4096.0f));
    return fminf(fmaxf(r, -128.0f), 127.0f);
}

__device__ __forceinline__ uint32_t smem_u32(const void* p) {
    uint32_t a;
    asm("{ .reg .u64 t; cvta.to.shared.u64 t, %1; cvt.u32.u64 %0, t; }" : "=r"(a) : "l"(p));
    return a;
}

#define CP16(dst, src)        asm volatile("cp.async.cg.shared.global [%0], [%1], 16;" :: "r"(dst), "l"(src))
#define CP16CA(dst, src)      asm volatile("cp.async.ca.shared.global [%0], [%1], 16;" :: "r"(dst), "l"(src))
#define CP16Z(dst, src, pred) asm volatile("cp.async.cg.shared.global [%0], [%1], 16, %2;" :: "r"(dst), "l"(src), "r"((pred) ? 16 : 0))
#define CP_COMMIT()           asm volatile("cp.async.commit_group;" ::: "memory")
#define CP_WAIT2()            asm volatile("cp.async.wait_group 2;" ::: "memory")
#define CP_WAIT1()            asm volatile("cp.async.wait_group 1;" ::: "memory")

// -------------------- fused prep: weight packing + input transpose --------------------
#define W1W (WIDTH * CIN / 4)
#define W2W (WIDTH * 9 * WIDTH / 4)
#define W3W (COUT * WIDTH / 4)
#define PACK_BLOCKS ((W1W + W2W + W3W + 255) / 256)   // 1092
#define XPOSE_BLOCKS (25 * 8 * 16)                    // 3200

__global__ void prep_kernel(const float* __restrict__ w1, const int* __restrict__ s1,
                            const float* __restrict__ w2, const int* __restrict__ s2,
                            const float* __restrict__ w3, const int* __restrict__ s3,
                            const int* __restrict__ x) {
    int b = blockIdx.x;
    int t = threadIdx.x;
    if (b < PACK_BLOCKS) {
        int wi = b * 256 + t;
        if (wi < W1W) {
            int v[4];
#pragma unroll
            for (int j = 0; j < 4; j++) { int idx = wi * 4 + j; v[j] = (int)w1[idx] * (1 << s1[idx]); }
            g_w1[wi] = pack4(v[0], v[1], v[2], v[3]);
        } else if (wi < W1W + W2W) {
            int k = wi - W1W;
            int co  = k / 576;
            int rr  = k - co * 576;
            int tap = rr >> 6;
            int cw  = rr & 63;
            int v[4];
#pragma unroll
            for (int j = 0; j < 4; j++) {
                int ci  = cw * 4 + j;
                int src = co * 2304 + ci * 9 + tap;
                v[j] = (int)w2[src] * (1 << s2[src]);
            }
            g_w2[k] = pack4(v[0], v[1], v[2], v[3]);
        } else if (wi < W1W + W2W + W3W) {
            int k = wi - W1W - W2W;
            int v[4];
#pragma unroll
            for (int j = 0; j < 4; j++) { int idx = k * 4 + j; v[j] = (int)w3[idx] * (1 << s3[idx]); }
            g_w3[k] = pack4(v[0], v[1], v[2], v[3]);
        }
        return;
    }
    int xb = b - PACK_BLOCKS;
    int bx = xb % 25;
    int by = (xb / 25) & 7;
    int n  = xb / 200;

    __shared__ uint32_t s[32][33];
    int phw_l = t & 31, phw = bx * 32 + phw_l;
#pragma unroll
    for (int l = 0; l < 4; l++) {
        int cwl = (t >> 5) + l * 8;
        uint32_t wv = 0;
        if (phw < PIX) {
            int ci = by * 128 + cwl * 4;
            const int* p = x + ((size_t)n * CIN + ci) * PIX + phw;
            wv = pack4(p[0], p[PIX], p[2 * PIX], p[3 * PIX]);
        }
        s[phw_l][cwl] = wv;
    }
    __syncthreads();
    int cwl2 = t & 31;
#pragma unroll
    for (int l = 0; l < 4; l++) {
        int pl = (t >> 5) + l * 8;
        int phw2 = bx * 32 + pl;
        if (phw2 < PIX)
            g_x8[((size_t)(n * PIX + phw2)) * 256 + by * 32 + cwl2] = s[pl][cwl2];
    }
}

// -------------------- IMMA tile machinery --------------------
#define RS      80
#define STAGES  4
#define ABUF    (64 * RS)
#define BBUF    (128 * RS)
#define SMEM12  (STAGES * (ABUF + BBUF))   // 61440
#define STAGES3 3
#define SMEM3   (2 * STAGES3 * BBUF)       // 61440

// warp tile 32 pos x 32 co (conv1/2)
__device__ __forceinline__ void compute_chunk64(uint32_t saBuf, uint32_t sbBuf,
                                                int m0, int n0, int lane,
                                                int acc[2][4][4]) {
#pragma unroll
    for (int ks = 0; ks < 2; ks++) {
        uint32_t af[2][4];
        uint32_t bf[4][2];
#pragma unroll
        for (int mi = 0; mi < 2; mi++) {
            uint32_t addr = saBuf + (uint32_t)((m0 + mi * 16 + (lane & 15)) * RS + ks * 32 + ((lane >> 4) << 4));
            asm volatile("ldmatrix.sync.aligned.m8n8.x4.shared.b16 {%0,%1,%2,%3}, [%4];"
                         : "=r"(af[mi][0]), "=r"(af[mi][1]), "=r"(af[mi][2]), "=r"(af[mi][3])
                         : "r"(addr));
        }
#pragma unroll
        for (int np = 0; np < 2; np++) {
            int rowb = n0 + np * 16 + ((lane >> 4) << 3) + (lane & 7);
            uint32_t addr = sbBuf + (uint32_t)(rowb * RS + ks * 32 + (((lane >> 3) & 1) << 4));
            asm volatile("ldmatrix.sync.aligned.m8n8.x4.shared.b16 {%0,%1,%2,%3}, [%4];"
                         : "=r"(bf[np * 2][0]), "=r"(bf[np * 2][1]),
                           "=r"(bf[np * 2 + 1][0]), "=r"(bf[np * 2 + 1][1])
                         : "r"(addr));
        }
#pragma unroll
        for (int mi = 0; mi < 2; mi++)
#pragma unroll
            for (int ni = 0; ni < 4; ni++)
                asm volatile("mma.sync.aligned.m16n8k32.row.col.s32.s8.s8.s32 "
                             "{%0,%1,%2,%3}, {%4,%5,%6,%7}, {%8,%9}, {%0,%1,%2,%3};"
                             : "+r"(acc[mi][ni][0]), "+r"(acc[mi][ni][1]),
                               "+r"(acc[mi][ni][2]), "+r"(acc[mi][ni][3])
                             : "r"(af[mi][0]), "r"(af[mi][1]), "r"(af[mi][2]), "r"(af[mi][3]),
                               "r"(bf[ni][0]), "r"(bf[ni][1]));
    }
}

// warp tile 64 pos x 32 co (conv3)
__device__ __forceinline__ void compute_chunk128(uint32_t saBuf, uint32_t sbBuf,
                                                 int m0, int n0, int lane,
                                                 int acc[4][4][4]) {
#pragma unroll
    for (int ks = 0; ks < 2; ks++) {
        uint32_t af[4][4];
        uint32_t bf[4][2];
#pragma unroll
        for (int mi = 0; mi < 4; mi++) {
            uint32_t addr = saBuf + (uint32_t)((m0 + mi * 16 + (lane & 15)) * RS + ks * 32 + ((lane >> 4) << 4));
            asm volatile("ldmatrix.sync.aligned.m8n8.x4.shared.b16 {%0,%1,%2,%3}, [%4];"
                         : "=r"(af[mi][0]), "=r"(af[mi][1]), "=r"(af[mi][2]), "=r"(af[mi][3])
                         : "r"(addr));
        }
#pragma unroll
        for (int np = 0; np < 2; np++) {
            int rowb = n0 + np * 16 + ((lane >> 4) << 3) + (lane & 7);
            uint32_t addr = sbBuf + (uint32_t)(rowb * RS + ks * 32 + (((lane >> 3) & 1) << 4));
            asm volatile("ldmatrix.sync.aligned.m8n8.x4.shared.b16 {%0,%1,%2,%3}, [%4];"
                         : "=r"(bf[np * 2][0]), "=r"(bf[np * 2][1]),
                           "=r"(bf[np * 2 + 1][0]), "=r"(bf[np * 2 + 1][1])
                         : "r"(addr));
        }
#pragma unroll
        for (int mi = 0; mi < 4; mi++)
#pragma unroll
            for (int ni = 0; ni < 4; ni++)
                asm volatile("mma.sync.aligned.m16n8k32.row.col.s32.s8.s8.s32 "
                             "{%0,%1,%2,%3}, {%4,%5,%6,%7}, {%8,%9}, {%0,%1,%2,%3};"
                             : "+r"(acc[mi][ni][0]), "+r"(acc[mi][ni][1]),
                               "+r"(acc[mi][ni][2]), "+r"(acc[mi][ni][3])
                             : "r"(af[mi][0]), "r"(af[mi][1]), "r"(af[mi][2]), "r"(af[mi][3]),
                               "r"(bf[ni][0]), "r"(bf[ni][1]));
    }
}

// ---- coalesced epilogue for conv1/conv2 ----
#define EP_RS 136
__device__ __forceinline__ void epi_act_coal(int acc[2][4][4], int posBase, int coBase,
                                             int m0, int n0, int t, int lane, int wid,
                                             int8_t* smem,
                                             const float* __restrict__ alpha,
                                             const float* __restrict__ beta,
                                             const int* __restrict__ q,
                                             uint32_t* __restrict__ dstw) {
    int*   sacc = (int*)smem;
    float* sal  = (float*)(smem + 64 * EP_RS * 4);
    float* sbe  = sal + 128;
    float* sqq  = sbe + 128;

    __syncthreads();
    if (t < 128) {
        int co = coBase + t;
        sal[t] = alpha[co];
        sbe[t] = beta[co];
        sqq[t] = exp2f((float)(q[co] + 12));
    }
#pragma unroll
    for (int mi = 0; mi < 2; mi++) {
#pragma unroll
        for (int ni = 0; ni < 4; ni++) {
            int pl = m0 + mi * 16 + (lane >> 2);
            int cl = n0 + ni * 8 + (lane & 3) * 2;
            sacc[pl * EP_RS + cl]           = acc[mi][ni][0];
            sacc[pl * EP_RS + cl + 1]       = acc[mi][ni][1];
            sacc[(pl + 8) * EP_RS + cl]     = acc[mi][ni][2];
            sacc[(pl + 8) * EP_RS + cl + 1] = acc[mi][ni][3];
        }
    }
    __syncthreads();
#pragma unroll
    for (int it = 0; it < 8; it++) {
        int pl = wid + it * 8;
        int cb = lane * 4;
        int4 v = *(int4*)&sacc[pl * EP_RS + cb];
        int b0 = bn_clip_relu(v.x, sal[cb],     sbe[cb],     sqq[cb]);
        int b1 = bn_clip_relu(v.y, sal[cb + 1], sbe[cb + 1], sqq[cb + 1]);
        int b2 = bn_clip_relu(v.z, sal[cb + 2], sbe[cb + 2], sqq[cb + 2]);
        int b3 = bn_clip_relu(v.w, sal[cb + 3], sbe[cb + 3], sqq[cb + 3]);
        dstw[(size_t)(posBase + pl) * 64 + (coBase >> 2) + lane] = pack4(b0, b1, b2, b3);
    }
}

// -------------------- conv1: tile 64x128, K=1024 (16 chunks) --------------------
__global__ void __launch_bounds__(256, 3) conv1_imma(const float* __restrict__ alpha,
                                                     const float* __restrict__ beta,
                                                     const int* __restrict__ q) {
    extern __shared__ int8_t smem[];
    int8_t* sA = smem;
    int8_t* sB = smem + STAGES * ABUF;
    int t = threadIdx.x, lane = t & 31, wid = t >> 5;
    int m0 = (wid >> 2) * 32, n0 = (wid & 3) * 32;
    int posBase = blockIdx.x * 64, coBase = blockIdx.y * 128;
    uint32_t sa32 = smem_u32(sA), sb32 = smem_u32(sB);
    const int8_t* gx = (const int8_t*)g_x8;
    const int8_t* gw = (const int8_t*)g_w1;

    int acc[2][4][4];
#pragma unroll
    for (int i = 0; i < 2; i++)
#pragma unroll
        for (int j = 0; j < 4; j++)
#pragma unroll
            for (int k = 0; k < 4; k++) acc[i][j][k] = 0;

    int rowA = t >> 2, offA = (t & 3) * 16;
    int rowB = t >> 1, offB = (t & 1) * 32;
    uint32_t dA = sa32 + rowA * RS + offA;
    uint32_t dB = sb32 + rowB * RS + offB;
    const int8_t* gA = gx + (size_t)(posBase + rowA) * CIN + offA;
    const int8_t* gB = gw + (size_t)(coBase + rowB) * CIN + offB;

    auto load = [&](int ch) {
        int st = ch & 3;
        CP16(dA + st * ABUF, gA + ch * 64);
        CP16CA(dB + st * BBUF,      gB + ch * 64);
        CP16CA(dB + st * BBUF + 16, gB + ch * 64 + 16);
    };

    load(0); CP_COMMIT(); load(1); CP_COMMIT(); load(2); CP_COMMIT();
    const int NCH = 16;
    for (int ch = 0; ch < NCH; ch++) {
        CP_WAIT2();
        __syncthreads();
        if (ch + 3 < NCH) load(ch + 3);
        CP_COMMIT();
        compute_chunk64(sa32 + (ch & 3) * ABUF, sb32 + (ch & 3) * BBUF, m0, n0, lane, acc);
    }
    epi_act_coal(acc, posBase, coBase, m0, n0, t, lane, wid, smem, alpha, beta, q, g_a1);
}

// -------------------- conv2: tile 64x128, 36 chunks --------------------
__global__ void __launch_bounds__(256, 3) conv2_imma(const float* __restrict__ alpha,
                                                     const float* __restrict__ beta,
                                                     const int* __restrict__ q) {
    extern __shared__ int8_t smem[];
    int8_t* sA = smem;
    int8_t* sB = smem + STAGES * ABUF;
    int t = threadIdx.x, lane = t & 31, wid = t >> 5;
    int m0 = (wid >> 2) * 32, n0 = (wid & 3) * 32;
    int posBase = blockIdx.x * 64, coBase = blockIdx.y * 128;
    uint32_t sa32 = smem_u32(sA), sb32 = smem_u32(sB);
    const int8_t* ga1 = (const int8_t*)g_a1;
    const int8_t* gw = (const int8_t*)g_w2;

    int acc[2][4][4];
#pragma unroll
    for (int i = 0; i < 2; i++)
#pragma unroll
        for (int j = 0; j < 4; j++)
#pragma unroll
            for (int k = 0; k < 4; k++) acc[i][j][k] = 0;

    int rowA = t >> 2, offA = (t & 3) * 16;
    int rowB = t >> 1, offB = (t & 1) * 32;
    uint32_t dA = sa32 + rowA * RS + offA;
    uint32_t dB = sb32 + rowB * RS + offB;
    int pos = posBase + rowA;
    int pimg = pos / PIX, prem = pos - pimg * PIX;
    int py = prem / 28, px = prem - py * 28;
    const int8_t* gB = gw + (size_t)(coBase + rowB) * 2304 + offB;

    auto load = [&](int ch) {
        int st = ch & 3;
        int tap = ch >> 2, kc = ch & 3;
        int dy = tap / 3 - 1, dx = tap - (tap / 3) * 3 - 1;
        int ys = py + dy, xs = px + dx;
        bool ok = (ys >= 0 && ys < 28 && xs >= 0 && xs < 28);
        const int8_t* gA = ga1 + ((size_t)(pimg * PIX + ys * 28 + xs) * WIDTH) + kc * 64 + offA;
        CP16Z(dA + st * ABUF, gA, ok);
        CP16CA(dB + st * BBUF,      gB + ch * 64);
        CP16CA(dB + st * BBUF + 16, gB + ch * 64 + 16);
    };

    load(0); CP_COMMIT(); load(1); CP_COMMIT(); load(2); CP_COMMIT();
    const int NCH = 36;
    for (int ch = 0; ch < NCH; ch++) {
        CP_WAIT2();
        __syncthreads();
        if (ch + 3 < NCH) load(ch + 3);
        CP_COMMIT();
        compute_chunk64(sa32 + (ch & 3) * ABUF, sb32 + (ch & 3) * BBUF, m0, n0, lane, acc);
    }
    epi_act_coal(acc, posBase, coBase, m0, n0, t, lane, wid, smem, alpha, beta, q, g_a2);
}

// -------------------- conv3: tile 128x128, K=256 (4 chunks), 3-stage, + residual --------------------
#define EP3_RS 68
__global__ void __launch_bounds__(256, 3) conv3_imma(const int* __restrict__ x,
                                                     const float* __restrict__ alpha,
                                                     const float* __restrict__ beta,
                                                     const int* __restrict__ q,
                                                     float* __restrict__ out) {
    extern __shared__ int8_t smem[];
    int8_t* sA = smem;
    int8_t* sB = smem + STAGES3 * BBUF;
    int t = threadIdx.x, lane = t & 31, wid = t >> 5;
    int m0 = (wid >> 2) * 64, n0 = (wid & 3) * 32;
    int posBase = blockIdx.x * 128, coBase = blockIdx.y * 128;
    uint32_t sa32 = smem_u32(sA), sb32 = smem_u32(sB);
    const int8_t* ga2 = (const int8_t*)g_a2;
    const int8_t* gw = (const int8_t*)g_w3;

    int acc[4][4][4];
#pragma unroll
    for (int i = 0; i < 4; i++)
#pragma unroll
        for (int j = 0; j < 4; j++)
#pragma unroll
            for (int k = 0; k < 4; k++) acc[i][j][k] = 0;

    int row = t >> 1, off = (t & 1) * 32;
    uint32_t dA = sa32 + row * RS + off;
    uint32_t dB = sb32 + row * RS + off;
    const int8_t* gA = ga2 + (size_t)(posBase + row) * WIDTH + off;
    const int8_t* gB = gw + (size_t)(coBase + row) * WIDTH + off;

    auto load = [&](int ch) {
        int st = ch % STAGES3;
        CP16(dA + st * BBUF,      gA + ch * 64);
        CP16(dA + st * BBUF + 16, gA + ch * 64 + 16);
        CP16CA(dB + st * BBUF,      gB + ch * 64);
        CP16CA(dB + st * BBUF + 16, gB + ch * 64 + 16);
    };

    load(0); CP_COMMIT(); load(1); CP_COMMIT();
    const int NCH = 4;
    for (int ch = 0; ch < NCH; ch++) {
        CP_WAIT1();
        __syncthreads();
        if (ch + 2 < NCH) load(ch + 2);
        CP_COMMIT();
        compute_chunk128(sa32 + (ch % STAGES3) * BBUF, sb32 + (ch % STAGES3) * BBUF, m0, n0, lane, acc);
    }

    int*   sacc = (int*)smem;
    float* sal  = (float*)(smem + 128 * EP3_RS * 4);
    float* sbe  = sal + 128;
    float* sqq  = sbe + 128;

    __syncthreads();
    if (t < 128) {
        int co = coBase + t;
        sal[t] = alpha[co];
        sbe[t] = beta[co];
        sqq[t] = exp2f((float)(q[co] + 12));
    }

#pragma unroll
    for (int pass = 0; pass < 2; pass++) {
        if (pass) __syncthreads();
#pragma unroll
        for (int mi2 = 0; mi2 < 2; mi2++) {
            int mi = pass * 2 + mi2;
#pragma unroll
            for (int ni = 0; ni < 4; ni++) {
#pragma unroll
                for (int k = 0; k < 4; k++) {
                    int pl = m0 + mi * 16 + (lane >> 2) + (k >> 1) * 8;
                    int r  = (pl & 31) + ((pl >> 6) * 32);
                    int cl = n0 + ni * 8 + (lane & 3) * 2 + (k & 1);
                    sacc[cl * EP3_RS + r] = acc[mi][ni][k];
                }
            }
        }
        __syncthreads();
        // vectorized store: each lane handles 4 consecutive rem (int4/float4)
#pragma unroll
        for (int it = 0; it < 8; it++) {
            int p    = it * 4 + (lane >> 3);     // (cl,run) pair index 0..31
            int cl   = wid * 16 + (p >> 1);
            int run  = p & 1;
            int rb   = run * 32 + (lane & 7) * 4;
            int4 av  = *(int4*)&sacc[cl * EP3_RS + rb];
            int pl   = (lane & 7) * 4 + run * 64 + pass * 32;
            int pos  = posBase + pl;
            int n    = pos / PIX, rem = pos - n * PIX;
            int co   = coBase + cl;
            size_t gi = ((size_t)n * COUT + co) * PIX + rem;
            int4 id4 = *(const int4*)(x + gi);
            float a = sal[cl], bb = sbe[cl], qq = sqq[cl];
            float4 o;
            o.x = fminf(fmaxf(bn_clip(av.x, a, bb, qq) + (float)id4.x, 0.0f), 127.0f);
            o.y = fminf(fmaxf(bn_clip(av.y, a, bb, qq) + (float)id4.y, 0.0f), 127.0f);
            o.z = fminf(fmaxf(bn_clip(av.z, a, bb, qq) + (float)id4.z, 0.0f), 127.0f);
            o.w = fminf(fmaxf(bn_clip(av.w, a, bb, qq) + (float)id4.w, 0.0f), 127.0f);
            *(float4*)(out + gi) = o;
        }
    }
}

// -------------------- launch --------------------
extern "C" void kernel_launch(void* const* d_in, const int* in_sizes, int n_in,
                              void* d_out, int out_size) {
    const int*   x   = (const int*)d_in[0];
    const float* w21 = (const float*)d_in[1];
    const int*   s1  = (const int*)d_in[2];
    const float* w22 = (const float*)d_in[3];
    const int*   s2  = (const int*)d_in[4];
    const float* w23 = (const float*)d_in[5];
    const int*   s3  = (const int*)d_in[6];
    const float* al1 = (const float*)d_in[7];
    const float* be1 = (const float*)d_in[8];
    const int*   q1  = (const int*)d_in[9];
    const float* al2 = (const float*)d_in[10];
    const float* be2 = (const float*)d_in[11];
    const int*   q2  = (const int*)d_in[12];
    const float* al3 = (const float*)d_in[13];
    const float* be3 = (const float*)d_in[14];
    const int*   q3  = (const int*)d_in[15];
    float* out = (float*)d_out;

    cudaFuncSetAttribute(conv1_imma, cudaFuncAttributeMaxDynamicSharedMemorySize, SMEM12);
    cudaFuncSetAttribute(conv2_imma, cudaFuncAttributeMaxDynamicSharedMemorySize, SMEM12);
    cudaFuncSetAttribute(conv3_imma, cudaFuncAttributeMaxDynamicSharedMemorySize, SMEM3);

    prep_kernel<<<PACK_BLOCKS + XPOSE_BLOCKS, 256>>>(w21, s1, w22, s2, w23, s3, x);

    conv1_imma<<<dim3(196, 2), 256, SMEM12>>>(al1, be1, q1);
    conv2_imma<<<dim3(196, 2), 256, SMEM12>>>(al2, be2, q2);
    conv3_imma<<<dim3(98, 8), 256, SMEM3>>>(x, al3, be3, q3, out);
}